// round 4
// baseline (speedup 1.0000x reference)
#include <cuda_runtime.h>

#define HH 50
#define TT 96
#define NPRED 12
#define NTH 128   // 4 warps -> SMSPs 0..3; two independent 64-thread "virtual blocks"
#define EPB 4     // batch elements per block (2 per thread, 2 per warp-pair)

typedef unsigned long long u64;

// ---- f32x2 packed helpers (FFMA2 path, sm_100+) ----
__device__ __forceinline__ u64 pk2(float lo, float hi) {
    u64 r;
    asm("mov.b64 %0, {%1,%2};" : "=l"(r) : "f"(lo), "f"(hi));
    return r;
}
__device__ __forceinline__ void upk2(u64 v, float &lo, float &hi) {
    asm("mov.b64 {%0,%1}, %2;" : "=f"(lo), "=f"(hi) : "l"(v));
}
__device__ __forceinline__ u64 ffma2(u64 a, u64 b, u64 c) {
    u64 d;
    asm("fma.rn.f32x2 %0, %1, %2, %3;" : "=l"(d) : "l"(a), "l"(b), "l"(c));
    return d;
}

// single-MUFU tanh (sm_75+), then sigmoid via tanh identity
__device__ __forceinline__ float ftanh(float x) {
    float y;
    asm("tanh.approx.f32 %0, %1;" : "=f"(y) : "f"(x));
    return y;
}
__device__ __forceinline__ float fsig(float x) {
    return fmaf(0.5f, ftanh(0.5f * x), 0.5f);
}

// pair-scoped barrier: warps {0,1} use id 1, warps {2,3} use id 2
__device__ __forceinline__ void pair_bar(int pr) {
    asm volatile("bar.sync %0, 64;" :: "r"(pr + 1) : "memory");
}

__global__ __launch_bounds__(NTH)
void lstm_recursive_kernel(const float* __restrict__ x,
                           const float* __restrict__ W_ih,
                           const float* __restrict__ W_hh,
                           const float* __restrict__ b_ih,
                           const float* __restrict__ b_hh,
                           const float* __restrict__ W_fc,
                           const float* __restrict__ b_fc,
                           float* __restrict__ out) {
    const int pr = threadIdx.x >> 6;           // warp pair 0/1
    const int j  = threadIdx.x & 63;           // lane within pair
    const int e0 = pr * 2;                     // first element slot of this pair
    const int b0 = blockIdx.x * EPB;           // first batch element of block

    __shared__ __align__(16) float sh[EPB][2][52];   // [elem][double-buffer][h padded]
    __shared__ float swin[EPB][TT + NPRED];          // sliding input windows
    __shared__ float sred[EPB][HH];                  // fc reduction scratch

#pragma unroll
    for (int q = 0; q < 2; q++)
        for (int i = j; i < TT; i += 64)
            swin[e0 + q][i] = x[(b0 + e0 + q) * TT + i];

    // thread j < 50 owns gate rows j, j+50, j+100, j+150 (i,f,g,o) for BOTH its elements
    u64 w[4][25];                    // 200 regs of packed W_hh pairs (shared across elements)
    float wih[4], bsum[4];
    float wfc = 0.0f;
    if (j < HH) {
#pragma unroll
        for (int g = 0; g < 4; g++) {
            const int row = g * HH + j;
            const float2* wr = (const float2*)(W_hh + row * HH);   // 8B aligned
#pragma unroll
            for (int k = 0; k < 25; k++) {
                float2 v = wr[k];
                w[g][k] = pk2(v.x, v.y);
            }
            wih[g]  = W_ih[row];
            bsum[g] = b_ih[row] + b_hh[row];
        }
        wfc = W_fc[j];
    }
    const float bfc = b_fc[0];

    for (int p = 0; p < NPRED; p++) {
        if (j < 52) {
#pragma unroll
            for (int q = 0; q < 2; q++) { sh[e0 + q][0][j] = 0.0f; sh[e0 + q][1][j] = 0.0f; }
        }
        float c[2], hnew[2];
#pragma unroll
        for (int q = 0; q < 2; q++) { c[q] = 0.0f; hnew[q] = 0.0f; }
        pair_bar(pr);

#pragma unroll 1
        for (int t = 0; t < TT; t++) {
            if (j < HH) {
                u64 a[2][4];
#pragma unroll
                for (int q = 0; q < 2; q++) {
                    const float xt = swin[e0 + q][p + t];
                    a[q][0] = pk2(fmaf(xt, wih[0], bsum[0]), 0.0f);
                    a[q][1] = pk2(fmaf(xt, wih[1], bsum[1]), 0.0f);
                    a[q][2] = pk2(fmaf(xt, wih[2], bsum[2]), 0.0f);
                    a[q][3] = pk2(fmaf(xt, wih[3], bsum[3]), 0.0f);
                }
                const ulonglong2* shvA = (const ulonglong2*)sh[e0][t & 1];
                const ulonglong2* shvB = (const ulonglong2*)sh[e0 + 1][t & 1];
#pragma unroll
                for (int cc = 0; cc < 12; cc++) {
                    ulonglong2 hvA = shvA[cc];         // LDS.128: hA[4cc..4cc+3]
                    ulonglong2 hvB = shvB[cc];         // LDS.128: hB[4cc..4cc+3]
                    a[0][0] = ffma2(w[0][2 * cc], hvA.x, a[0][0]);
                    a[0][1] = ffma2(w[1][2 * cc], hvA.x, a[0][1]);
                    a[0][2] = ffma2(w[2][2 * cc], hvA.x, a[0][2]);
                    a[0][3] = ffma2(w[3][2 * cc], hvA.x, a[0][3]);
                    a[1][0] = ffma2(w[0][2 * cc], hvB.x, a[1][0]);
                    a[1][1] = ffma2(w[1][2 * cc], hvB.x, a[1][1]);
                    a[1][2] = ffma2(w[2][2 * cc], hvB.x, a[1][2]);
                    a[1][3] = ffma2(w[3][2 * cc], hvB.x, a[1][3]);
                    a[0][0] = ffma2(w[0][2 * cc + 1], hvA.y, a[0][0]);
                    a[0][1] = ffma2(w[1][2 * cc + 1], hvA.y, a[0][1]);
                    a[0][2] = ffma2(w[2][2 * cc + 1], hvA.y, a[0][2]);
                    a[0][3] = ffma2(w[3][2 * cc + 1], hvA.y, a[0][3]);
                    a[1][0] = ffma2(w[0][2 * cc + 1], hvB.y, a[1][0]);
                    a[1][1] = ffma2(w[1][2 * cc + 1], hvB.y, a[1][1]);
                    a[1][2] = ffma2(w[2][2 * cc + 1], hvB.y, a[1][2]);
                    a[1][3] = ffma2(w[3][2 * cc + 1], hvB.y, a[1][3]);
                }
                {
                    u64 htA = ((const u64*)sh[e0][t & 1])[24];       // hA[48], hA[49]
                    u64 htB = ((const u64*)sh[e0 + 1][t & 1])[24];
                    a[0][0] = ffma2(w[0][24], htA, a[0][0]);
                    a[0][1] = ffma2(w[1][24], htA, a[0][1]);
                    a[0][2] = ffma2(w[2][24], htA, a[0][2]);
                    a[0][3] = ffma2(w[3][24], htA, a[0][3]);
                    a[1][0] = ffma2(w[0][24], htB, a[1][0]);
                    a[1][1] = ffma2(w[1][24], htB, a[1][1]);
                    a[1][2] = ffma2(w[2][24], htB, a[1][2]);
                    a[1][3] = ffma2(w[3][24], htB, a[1][3]);
                }
#pragma unroll
                for (int q = 0; q < 2; q++) {
                    float l0, h0, l1, h1, l2, h2, l3, h3;
                    upk2(a[q][0], l0, h0);
                    upk2(a[q][1], l1, h1);
                    upk2(a[q][2], l2, h2);
                    upk2(a[q][3], l3, h3);
                    const float i_ = fsig(l0 + h0);
                    const float f_ = fsig(l1 + h1);
                    const float g_ = ftanh(l2 + h2);
                    const float o_ = fsig(l3 + h3);
                    c[q]    = fmaf(f_, c[q], i_ * g_);
                    hnew[q] = o_ * ftanh(c[q]);
                    sh[e0 + q][(t + 1) & 1][j] = hnew[q];   // write buffer (readers use t&1)
                }
            }
            pair_bar(pr);                          // new h visible for next step (pair only)
        }

        // prediction: dot(h, W_fc) + b_fc (one lane per element reduces)
        if (j < HH) {
#pragma unroll
            for (int q = 0; q < 2; q++) sred[e0 + q][j] = hnew[q] * wfc;
        }
        pair_bar(pr);
        if (j < 2) {
            float s = bfc;
#pragma unroll
            for (int k = 0; k < HH; k++) s += sred[e0 + j][k];
            swin[e0 + j][TT + p] = s;              // slide window
            out[(b0 + e0 + j) * NPRED + p] = s;
        }
        pair_bar(pr);
    }
}

extern "C" void kernel_launch(void* const* d_in, const int* in_sizes, int n_in,
                              void* d_out, int out_size) {
    const float* x    = (const float*)d_in[0];
    const float* W_ih = (const float*)d_in[1];
    const float* W_hh = (const float*)d_in[2];
    const float* b_ih = (const float*)d_in[3];
    const float* b_hh = (const float*)d_in[4];
    const float* W_fc = (const float*)d_in[5];
    const float* b_fc = (const float*)d_in[6];
    float* out = (float*)d_out;

    const int B = out_size / NPRED;               // 1024
    lstm_recursive_kernel<<<B / EPB, NTH>>>(x, W_ih, W_hh, b_ih, b_hh, W_fc, b_fc, out);
}